// round 1
// baseline (speedup 1.0000x reference)
#include <cuda_runtime.h>

// ---------------------------------------------------------------------------
// NCF_Feature: fused bag + one-hot lookup + feature GEMVs + batchnorm + MLP
// Inputs (metadata order):
//  0 user_idx(i32,unused) 1 item_idx(i32,unused)
//  2 user_feature[16384,128] 3 item_feature[16384,128]
//  4 user_tag[16384,4096]    5 item_tag[16384,4096]
//  6 W_user[10,128] 7 b_user[10] 8 W_item[10,128] 9 b_item[10]
// 10 E_user_tag[4096,5] 11 E_item_tag[4096,5]
// 12 g1[10] 13 be1[10] 14 g2[10] 15 be2[10]
// 16 W1[64,30] 17 b1[64] 18 W2[32,64] 19 b2[32] 20 W3[1,32] 21 b3[1]
// Output: [16384,1] f32
// ---------------------------------------------------------------------------

#define B_ROWS 16384
#define TAGS   4096
#define GMAIN  256            // main-kernel blocks; 64 rows per block

// Scratch (allocation-free rule: __device__ globals)
__device__ float g_feat[(size_t)B_ROWS * 32];   // [B][32]: u(10) eut(5) i(10) eit(5) pad(2)
__device__ float g_part[GMAIN * 40];            // per-block: sum[20], sumsq[20]
__device__ float g_scale[20];
__device__ float g_shift[20];

__device__ __forceinline__ float warpsum(float v) {
#pragma unroll
    for (int o = 16; o; o >>= 1) v += __shfl_xor_sync(0xffffffffu, v, o);
    return v;
}

// ===========================================================================
// Kernel 1: the HBM-bound streamer.
//  - smem: E_item_tag SoA (5*4096), W_user, W_item, stat-reduce scratch
//  - each warp: 2 quads of 4 rows (E loads amortized x4)
//  - deterministic per-block BN partial sums (no float atomics)
// ===========================================================================
__global__ void __launch_bounds__(256, 2)
k_main(const float* __restrict__ uf_g, const float* __restrict__ if_g,
       const float* __restrict__ ut_g, const float* __restrict__ it_g,
       const float* __restrict__ Wu,   const float* __restrict__ bu,
       const float* __restrict__ Wi,   const float* __restrict__ bi,
       const float* __restrict__ Eu,   const float* __restrict__ Ei)
{
    extern __shared__ float sm[];
    float* sE   = sm;                 // 5*4096 floats, SoA: sE[k*4096 + t]
    float* sWu  = sE + 5 * TAGS;      // 10*128
    float* sWi  = sWu + 1280;         // 10*128
    float* sRed = sWi + 1280;         // 8*40

    const int tid = threadIdx.x;

    // Stage E_item_tag [4096,5] -> SoA shared
    for (int i = tid; i < TAGS; i += 256) {
        float e0 = Ei[i * 5 + 0], e1 = Ei[i * 5 + 1], e2 = Ei[i * 5 + 2];
        float e3 = Ei[i * 5 + 3], e4 = Ei[i * 5 + 4];
        sE[0 * TAGS + i] = e0; sE[1 * TAGS + i] = e1; sE[2 * TAGS + i] = e2;
        sE[3 * TAGS + i] = e3; sE[4 * TAGS + i] = e4;
    }
    for (int i = tid; i < 1280; i += 256) { sWu[i] = Wu[i]; sWi[i] = Wi[i]; }
    __syncthreads();

    const int warp = tid >> 5, lane = tid & 31;
    const int rowbase = blockIdx.x * 64 + warp * 8;
    const float4* sE4 = (const float4*)sE;
    const float4* sWu4 = (const float4*)sWu;
    const float4* sWi4 = (const float4*)sWi;

    float su = 0.f, sq = 0.f;   // per-lane BN partials (lanes 0..19 meaningful)

#pragma unroll 1
    for (int q = 0; q < 2; q++) {
        const int r0 = rowbase + q * 4;

        // ---- weighted tag bag: 4 rows share each E load ----
        const float4* t0 = (const float4*)(ut_g + (size_t)(r0 + 0) * TAGS);
        const float4* t1 = (const float4*)(ut_g + (size_t)(r0 + 1) * TAGS);
        const float4* t2 = (const float4*)(ut_g + (size_t)(r0 + 2) * TAGS);
        const float4* t3 = (const float4*)(ut_g + (size_t)(r0 + 3) * TAGS);
        float acc[4][5];
#pragma unroll
        for (int r = 0; r < 4; r++)
#pragma unroll
            for (int k = 0; k < 5; k++) acc[r][k] = 0.f;

        for (int i = lane; i < TAGS / 4; i += 32) {
            float4 tg[4];
            tg[0] = t0[i]; tg[1] = t1[i]; tg[2] = t2[i]; tg[3] = t3[i];
            float4 ee[5];
#pragma unroll
            for (int k = 0; k < 5; k++) ee[k] = sE4[k * (TAGS / 4) + i];
#pragma unroll
            for (int r = 0; r < 4; r++) {
#pragma unroll
                for (int k = 0; k < 5; k++) {
                    acc[r][k] += tg[r].x * ee[k].x + tg[r].y * ee[k].y
                               + tg[r].z * ee[k].z + tg[r].w * ee[k].w;
                }
            }
        }
#pragma unroll
        for (int r = 0; r < 4; r++) {
#pragma unroll
            for (int k = 0; k < 5; k++) {
                float s = warpsum(acc[r][k]) * 0.1f;
                if (lane == k) g_feat[(size_t)(r0 + r) * 32 + 10 + k] = s;
            }
        }

        // ---- per-row: feature GEMVs + one-hot search ----
#pragma unroll 1
        for (int r = 0; r < 4; r++) {
            const int rr = r0 + r;
            float4 xu = ((const float4*)(uf_g + (size_t)rr * 128))[lane];
            float4 xi = ((const float4*)(if_g + (size_t)rr * 128))[lane];
#pragma unroll
            for (int j = 0; j < 10; j++) {
                float4 wu = sWu4[j * 32 + lane];
                float s = warpsum(xu.x * wu.x + xu.y * wu.y + xu.z * wu.z + xu.w * wu.w) + bu[j];
                if (lane == j) { g_feat[(size_t)rr * 32 + j] = s; su += s; sq += s * s; }
                float4 wi = sWi4[j * 32 + lane];
                float s2 = warpsum(xi.x * wi.x + xi.y * wi.y + xi.z * wi.z + xi.w * wi.w) + bi[j];
                if (lane == j + 10) { g_feat[(size_t)rr * 32 + 15 + j] = s2; su += s2; sq += s2 * s2; }
            }

            // one-hot search over item_tag row: 1024-elem chunks, 8 independent
            // LDG.128 per chunk before the ballot (short latency chain + early exit)
            const float4* it4 = (const float4*)(it_g + (size_t)rr * TAGS);
            int hot = 0;
#pragma unroll 1
            for (int base = 0; base < 1024; base += 256) {
                float4 v[8];
#pragma unroll
                for (int k = 0; k < 8; k++) v[k] = it4[base + k * 32 + lane];
                int m = 0;
#pragma unroll
                for (int k = 0; k < 8; k++) {
                    m |= (v[k].x == 1.f) << (k * 4 + 0);
                    m |= (v[k].y == 1.f) << (k * 4 + 1);
                    m |= (v[k].z == 1.f) << (k * 4 + 2);
                    m |= (v[k].w == 1.f) << (k * 4 + 3);
                }
                unsigned bal = __ballot_sync(0xffffffffu, m != 0);
                if (bal) {
                    int src = __ffs(bal) - 1;
                    int mm  = __shfl_sync(0xffffffffu, m, src);
                    int bit = __ffs(mm) - 1;
                    hot = 4 * (base + (bit >> 2) * 32 + src) + (bit & 3);
                    break;
                }
            }
            if (lane < 5) g_feat[(size_t)rr * 32 + 25 + lane] = Eu[(size_t)hot * 5 + lane];
        }
    }

    // ---- deterministic per-block BN partials ----
    if (lane < 20) { sRed[warp * 40 + lane] = su; sRed[warp * 40 + 20 + lane] = sq; }
    __syncthreads();
    if (tid < 40) {
        float s = 0.f;
#pragma unroll
        for (int w = 0; w < 8; w++) s += sRed[w * 40 + tid];
        g_part[blockIdx.x * 40 + tid] = s;
    }
}

// ===========================================================================
// Kernel 2: reduce 256 block partials -> BN scale/shift (deterministic)
// ===========================================================================
__global__ void k_stats(const float* __restrict__ g1, const float* __restrict__ be1,
                        const float* __restrict__ g2, const float* __restrict__ be2)
{
    __shared__ float red[8][40];
    __shared__ float tot[40];
    const int tid = threadIdx.x;            // blockDim = 320
    const int j = tid % 40, g = tid / 40;
    if (tid < 320) {
        float s = 0.f;
#pragma unroll 4
        for (int i = 0; i < 32; i++) s += g_part[(g * 32 + i) * 40 + j];
        red[g][j] = s;
    }
    __syncthreads();
    if (tid < 40) {
        float s = 0.f;
#pragma unroll
        for (int gg = 0; gg < 8; gg++) s += red[gg][tid];
        tot[tid] = s;
    }
    __syncthreads();
    if (tid < 20) {
        float mean = tot[tid] * (1.f / B_ROWS);
        float var  = tot[20 + tid] * (1.f / B_ROWS) - mean * mean;  // biased
        float ga = (tid < 10) ? g1[tid]  : g2[tid - 10];
        float be = (tid < 10) ? be1[tid] : be2[tid - 10];
        float sc = ga * rsqrtf(var + 1e-5f);
        g_scale[tid] = sc;
        g_shift[tid] = be - mean * sc;
    }
}

// ===========================================================================
// Kernel 3: normalize + 30->64->32->1 ReLU MLP, one thread per row
// ===========================================================================
__global__ void __launch_bounds__(256)
k_mlp(const float* __restrict__ W1, const float* __restrict__ b1,
      const float* __restrict__ W2, const float* __restrict__ b2,
      const float* __restrict__ W3, const float* __restrict__ b3,
      float* __restrict__ out)
{
    __shared__ float sW1[64 * 30], sb1[64], sW2[32 * 64], sb2[32], sW3[32];
    __shared__ float ssc[20], ssh[20], sb3;
    const int tid = threadIdx.x;
    for (int i = tid; i < 64 * 30; i += 256) sW1[i] = W1[i];
    for (int i = tid; i < 32 * 64; i += 256) sW2[i] = W2[i];
    if (tid < 64) sb1[tid] = b1[tid];
    if (tid < 32) { sb2[tid] = b2[tid]; sW3[tid] = W3[tid]; }
    if (tid < 20) { ssc[tid] = g_scale[tid]; ssh[tid] = g_shift[tid]; }
    if (tid == 0) sb3 = b3[0];
    __syncthreads();

    const int r = blockIdx.x * 256 + tid;
    const float4* fp = (const float4*)(g_feat + (size_t)r * 32);
    float x[30];
    float4 v[8];
#pragma unroll
    for (int i = 0; i < 8; i++) v[i] = fp[i];
#pragma unroll
    for (int i = 0; i < 7; i++) {
        x[i * 4 + 0] = v[i].x; x[i * 4 + 1] = v[i].y;
        x[i * 4 + 2] = v[i].z; x[i * 4 + 3] = v[i].w;
    }
    x[28] = v[7].x; x[29] = v[7].y;

    // batchnorm: user cols 0..9 (stats 0..9), item cols 15..24 (stats 10..19)
#pragma unroll
    for (int j = 0; j < 10; j++) {
        x[j]      = x[j]      * ssc[j]      + ssh[j];
        x[15 + j] = x[15 + j] * ssc[10 + j] + ssh[10 + j];
    }

    float h1[64];
#pragma unroll
    for (int o = 0; o < 64; o++) {
        float s = sb1[o];
#pragma unroll
        for (int i = 0; i < 30; i++) s += sW1[o * 30 + i] * x[i];
        h1[o] = fmaxf(s, 0.f);
    }
    float h2[32];
#pragma unroll
    for (int o = 0; o < 32; o++) {
        float s = sb2[o];
#pragma unroll
        for (int i = 0; i < 64; i++) s += sW2[o * 64 + i] * h1[i];
        h2[o] = fmaxf(s, 0.f);
    }
    float s = sb3;
#pragma unroll
    for (int i = 0; i < 32; i++) s += sW3[i] * h2[i];
    out[r] = fmaxf(s, 0.f);
}

// ===========================================================================
extern "C" void kernel_launch(void* const* d_in, const int* in_sizes, int n_in,
                              void* d_out, int out_size)
{
    (void)in_sizes; (void)n_in; (void)out_size;
    const float* user_feature = (const float*)d_in[2];
    const float* item_feature = (const float*)d_in[3];
    const float* user_tag     = (const float*)d_in[4];
    const float* item_tag     = (const float*)d_in[5];
    const float* W_user = (const float*)d_in[6];
    const float* b_user = (const float*)d_in[7];
    const float* W_item = (const float*)d_in[8];
    const float* b_item = (const float*)d_in[9];
    const float* E_user_tag = (const float*)d_in[10];
    const float* E_item_tag = (const float*)d_in[11];
    const float* g1  = (const float*)d_in[12];
    const float* be1 = (const float*)d_in[13];
    const float* g2  = (const float*)d_in[14];
    const float* be2 = (const float*)d_in[15];
    const float* W1 = (const float*)d_in[16];
    const float* b1 = (const float*)d_in[17];
    const float* W2 = (const float*)d_in[18];
    const float* b2 = (const float*)d_in[19];
    const float* W3 = (const float*)d_in[20];
    const float* b3 = (const float*)d_in[21];

    const int smem_bytes = (5 * TAGS + 1280 + 1280 + 320) * (int)sizeof(float); // 93440
    cudaFuncSetAttribute(k_main, cudaFuncAttributeMaxDynamicSharedMemorySize, smem_bytes);

    k_main<<<GMAIN, 256, smem_bytes>>>(user_feature, item_feature, user_tag, item_tag,
                                       W_user, b_user, W_item, b_item,
                                       E_user_tag, E_item_tag);
    k_stats<<<1, 320>>>(g1, be1, g2, be2);
    k_mlp<<<64, 256>>>(W1, b1, W2, b2, W3, b3, (float*)d_out);
}

// round 2
// speedup vs baseline: 1.0708x; 1.0708x over previous
#include <cuda_runtime.h>

// ---------------------------------------------------------------------------
// NCF_Feature: fused bag + one-hot lookup + feature GEMVs + batchnorm + MLP
// ---------------------------------------------------------------------------

#define B_ROWS 16384
#define TAGS   4096
#define GMAIN  256            // main-kernel blocks; 64 rows per block
#define NWARP  16             // warps per main block (512 threads)

// Scratch (allocation-free rule: __device__ globals)
__device__ float g_feat[(size_t)B_ROWS * 32];   // [B][32]: u(10) eut(5) i(10) eit(5) pad(2)
__device__ float g_part[GMAIN * 40];            // per-block: sum[20], sumsq[20]
__device__ float g_scale[20];
__device__ float g_shift[20];

__device__ __forceinline__ float warpsum(float v) {
#pragma unroll
    for (int o = 16; o; o >>= 1) v += __shfl_xor_sync(0xffffffffu, v, o);
    return v;
}

// ===========================================================================
// Kernel 1: HBM streamer. 512 threads, 2 CTA/SM -> 32 warps/SM.
//  - smem: E_item_tag SoA (5*4096), W_user, W_item, stat scratch
//  - each warp: 4 rows as 2 quads of 2 (regs <= 64)
//  - deterministic per-block BN partial sums
// ===========================================================================
__global__ void __launch_bounds__(512, 2)
k_main(const float* __restrict__ uf_g, const float* __restrict__ if_g,
       const float* __restrict__ ut_g, const float* __restrict__ it_g,
       const float* __restrict__ Wu,   const float* __restrict__ bu,
       const float* __restrict__ Wi,   const float* __restrict__ bi,
       const float* __restrict__ Eu,   const float* __restrict__ Ei)
{
    extern __shared__ float sm[];
    float* sE   = sm;                 // 5*4096 floats, SoA: sE[k*4096 + t]
    float* sWu  = sE + 5 * TAGS;      // 10*128
    float* sWi  = sWu + 1280;         // 10*128
    float* sRed = sWi + 1280;         // NWARP*40

    const int tid = threadIdx.x;

    // Stage E_item_tag [4096,5] -> SoA shared
    for (int i = tid; i < TAGS; i += 512) {
        float e0 = Ei[i * 5 + 0], e1 = Ei[i * 5 + 1], e2 = Ei[i * 5 + 2];
        float e3 = Ei[i * 5 + 3], e4 = Ei[i * 5 + 4];
        sE[0 * TAGS + i] = e0; sE[1 * TAGS + i] = e1; sE[2 * TAGS + i] = e2;
        sE[3 * TAGS + i] = e3; sE[4 * TAGS + i] = e4;
    }
    for (int i = tid; i < 1280; i += 512) { sWu[i] = Wu[i]; sWi[i] = Wi[i]; }
    __syncthreads();

    const int warp = tid >> 5, lane = tid & 31;
    const int rowbase = blockIdx.x * 64 + warp * 4;
    const float4* sE4  = (const float4*)sE;
    const float4* sWu4 = (const float4*)sWu;
    const float4* sWi4 = (const float4*)sWi;

    float su = 0.f, sq = 0.f;   // per-lane BN partials (lanes 0..19 meaningful)

#pragma unroll 1
    for (int q = 0; q < 2; q++) {
        const int r0 = rowbase + q * 2;

        // ---- weighted tag bag: 2 rows share each E load ----
        const float4* t0 = (const float4*)(ut_g + (size_t)(r0 + 0) * TAGS);
        const float4* t1 = (const float4*)(ut_g + (size_t)(r0 + 1) * TAGS);
        float acc[2][5];
#pragma unroll
        for (int r = 0; r < 2; r++)
#pragma unroll
            for (int k = 0; k < 5; k++) acc[r][k] = 0.f;

#pragma unroll 1
        for (int i = lane; i < TAGS / 4; i += 32) {
            float4 tg0 = t0[i];
            float4 tg1 = t1[i];
            float4 ee[5];
#pragma unroll
            for (int k = 0; k < 5; k++) ee[k] = sE4[k * (TAGS / 4) + i];
#pragma unroll
            for (int k = 0; k < 5; k++) {
                acc[0][k] += tg0.x * ee[k].x + tg0.y * ee[k].y
                           + tg0.z * ee[k].z + tg0.w * ee[k].w;
                acc[1][k] += tg1.x * ee[k].x + tg1.y * ee[k].y
                           + tg1.z * ee[k].z + tg1.w * ee[k].w;
            }
        }
#pragma unroll
        for (int r = 0; r < 2; r++) {
#pragma unroll
            for (int k = 0; k < 5; k++) {
                float s = warpsum(acc[r][k]) * 0.1f;
                if (lane == k) g_feat[(size_t)(r0 + r) * 32 + 10 + k] = s;
            }
        }

        // ---- per-row: feature GEMVs + one-hot search ----
#pragma unroll 1
        for (int r = 0; r < 2; r++) {
            const int rr = r0 + r;
            float4 xu = ((const float4*)(uf_g + (size_t)rr * 128))[lane];
            float4 xi = ((const float4*)(if_g + (size_t)rr * 128))[lane];
#pragma unroll
            for (int j = 0; j < 10; j++) {
                float4 wu = sWu4[j * 32 + lane];
                float s = warpsum(xu.x * wu.x + xu.y * wu.y + xu.z * wu.z + xu.w * wu.w) + bu[j];
                if (lane == j) { g_feat[(size_t)rr * 32 + j] = s; su += s; sq += s * s; }
                float4 wi = sWi4[j * 32 + lane];
                float s2 = warpsum(xi.x * wi.x + xi.y * wi.y + xi.z * wi.z + xi.w * wi.w) + bi[j];
                if (lane == j + 10) { g_feat[(size_t)rr * 32 + 15 + j] = s2; su += s2; sq += s2 * s2; }
            }

            // one-hot search: 512-elem chunks, 4 independent LDG.128 per chunk
            // before each ballot (early exit; expected read ~56% of row)
            const float4* it4 = (const float4*)(it_g + (size_t)rr * TAGS);
            int hot = 0;
#pragma unroll 1
            for (int base = 0; base < 1024; base += 128) {
                float4 v[4];
#pragma unroll
                for (int k = 0; k < 4; k++) v[k] = it4[base + k * 32 + lane];
                int m = 0;
#pragma unroll
                for (int k = 0; k < 4; k++) {
                    m |= (v[k].x == 1.f) << (k * 4 + 0);
                    m |= (v[k].y == 1.f) << (k * 4 + 1);
                    m |= (v[k].z == 1.f) << (k * 4 + 2);
                    m |= (v[k].w == 1.f) << (k * 4 + 3);
                }
                unsigned bal = __ballot_sync(0xffffffffu, m != 0);
                if (bal) {
                    int src = __ffs(bal) - 1;
                    int mm  = __shfl_sync(0xffffffffu, m, src);
                    int bit = __ffs(mm) - 1;
                    hot = 4 * (base + (bit >> 2) * 32 + src) + (bit & 3);
                    break;
                }
            }
            if (lane < 5) g_feat[(size_t)rr * 32 + 25 + lane] = Eu[(size_t)hot * 5 + lane];
        }
    }

    // ---- deterministic per-block BN partials ----
    if (lane < 20) { sRed[warp * 40 + lane] = su; sRed[warp * 40 + 20 + lane] = sq; }
    __syncthreads();
    if (tid < 40) {
        float s = 0.f;
#pragma unroll
        for (int w = 0; w < NWARP; w++) s += sRed[w * 40 + tid];
        g_part[blockIdx.x * 40 + tid] = s;
    }
}

// ===========================================================================
// Kernel 2: reduce 256 block partials -> BN scale/shift (deterministic)
// ===========================================================================
__global__ void k_stats(const float* __restrict__ g1, const float* __restrict__ be1,
                        const float* __restrict__ g2, const float* __restrict__ be2)
{
    __shared__ float red[8][40];
    __shared__ float tot[40];
    const int tid = threadIdx.x;            // blockDim = 320
    const int j = tid % 40, g = tid / 40;
    if (tid < 320) {
        float s = 0.f;
#pragma unroll 4
        for (int i = 0; i < 32; i++) s += g_part[(g * 32 + i) * 40 + j];
        red[g][j] = s;
    }
    __syncthreads();
    if (tid < 40) {
        float s = 0.f;
#pragma unroll
        for (int gg = 0; gg < 8; gg++) s += red[gg][tid];
        tot[tid] = s;
    }
    __syncthreads();
    if (tid < 20) {
        float mean = tot[tid] * (1.f / B_ROWS);
        float var  = tot[20 + tid] * (1.f / B_ROWS) - mean * mean;  // biased
        float ga = (tid < 10) ? g1[tid]  : g2[tid - 10];
        float be = (tid < 10) ? be1[tid] : be2[tid - 10];
        float sc = ga * rsqrtf(var + 1e-5f);
        g_scale[tid] = sc;
        g_shift[tid] = be - mean * sc;
    }
}

// ===========================================================================
// Kernel 3: normalize + 30->64->32->1 ReLU MLP, one thread per row
// ===========================================================================
__global__ void __launch_bounds__(128)
k_mlp(const float* __restrict__ W1, const float* __restrict__ b1,
      const float* __restrict__ W2, const float* __restrict__ b2,
      const float* __restrict__ W3, const float* __restrict__ b3,
      float* __restrict__ out)
{
    __shared__ float sW1[64 * 30], sb1[64], sW2[32 * 64], sb2[32], sW3[32];
    __shared__ float ssc[20], ssh[20], sb3;
    const int tid = threadIdx.x;
    for (int i = tid; i < 64 * 30; i += 128) sW1[i] = W1[i];
    for (int i = tid; i < 32 * 64; i += 128) sW2[i] = W2[i];
    if (tid < 64) sb1[tid] = b1[tid];
    if (tid < 32) { sb2[tid] = b2[tid]; sW3[tid] = W3[tid]; }
    if (tid < 20) { ssc[tid] = g_scale[tid]; ssh[tid] = g_shift[tid]; }
    if (tid == 0) sb3 = b3[0];
    __syncthreads();

    const int r = blockIdx.x * 128 + tid;
    const float4* fp = (const float4*)(g_feat + (size_t)r * 32);
    float x[30];
    float4 v[8];
#pragma unroll
    for (int i = 0; i < 8; i++) v[i] = fp[i];
#pragma unroll
    for (int i = 0; i < 7; i++) {
        x[i * 4 + 0] = v[i].x; x[i * 4 + 1] = v[i].y;
        x[i * 4 + 2] = v[i].z; x[i * 4 + 3] = v[i].w;
    }
    x[28] = v[7].x; x[29] = v[7].y;

    // batchnorm: user cols 0..9 (stats 0..9), item cols 15..24 (stats 10..19)
#pragma unroll
    for (int j = 0; j < 10; j++) {
        x[j]      = x[j]      * ssc[j]      + ssh[j];
        x[15 + j] = x[15 + j] * ssc[10 + j] + ssh[10 + j];
    }

    float h1[64];
#pragma unroll
    for (int o = 0; o < 64; o++) {
        float s = sb1[o];
#pragma unroll
        for (int i = 0; i < 30; i++) s += sW1[o * 30 + i] * x[i];
        h1[o] = fmaxf(s, 0.f);
    }
    float h2[32];
#pragma unroll
    for (int o = 0; o < 32; o++) {
        float s = sb2[o];
#pragma unroll
        for (int i = 0; i < 64; i++) s += sW2[o * 64 + i] * h1[i];
        h2[o] = fmaxf(s, 0.f);
    }
    float s = sb3;
#pragma unroll
    for (int i = 0; i < 32; i++) s += sW3[i] * h2[i];
    out[r] = fmaxf(s, 0.f);
}

// ===========================================================================
extern "C" void kernel_launch(void* const* d_in, const int* in_sizes, int n_in,
                              void* d_out, int out_size)
{
    (void)in_sizes; (void)n_in; (void)out_size;
    const float* user_feature = (const float*)d_in[2];
    const float* item_feature = (const float*)d_in[3];
    const float* user_tag     = (const float*)d_in[4];
    const float* item_tag     = (const float*)d_in[5];
    const float* W_user = (const float*)d_in[6];
    const float* b_user = (const float*)d_in[7];
    const float* W_item = (const float*)d_in[8];
    const float* b_item = (const float*)d_in[9];
    const float* E_user_tag = (const float*)d_in[10];
    const float* E_item_tag = (const float*)d_in[11];
    const float* g1  = (const float*)d_in[12];
    const float* be1 = (const float*)d_in[13];
    const float* g2  = (const float*)d_in[14];
    const float* be2 = (const float*)d_in[15];
    const float* W1 = (const float*)d_in[16];
    const float* b1 = (const float*)d_in[17];
    const float* W2 = (const float*)d_in[18];
    const float* b2 = (const float*)d_in[19];
    const float* W3 = (const float*)d_in[20];
    const float* b3 = (const float*)d_in[21];

    const int smem_bytes = (5 * TAGS + 1280 + 1280 + NWARP * 40) * (int)sizeof(float);
    cudaFuncSetAttribute(k_main, cudaFuncAttributeMaxDynamicSharedMemorySize, smem_bytes);

    k_main<<<GMAIN, 512, smem_bytes>>>(user_feature, item_feature, user_tag, item_tag,
                                       W_user, b_user, W_item, b_item,
                                       E_user_tag, E_item_tag);
    k_stats<<<1, 320>>>(g1, be1, g2, be2);
    k_mlp<<<128, 128>>>(W1, b1, W2, b2, W3, b3, (float*)d_out);
}